// round 12
// baseline (speedup 1.0000x reference)
#include <cuda_runtime.h>
#include <cuda_fp16.h>
#include <cstdint>

// ---------------- problem constants ----------------
#define Bc   2
#define CC   128
#define HH   128
#define WW   128
#define HWp  (HH*WW)
#define NHh  8
#define HDd  16
#define SCALEF 0.25f

typedef unsigned long long u64;

// ---------------- scratch ----------------
// paired half2 input planes: qi<32: (x-pair 8ch+kk, x-pair 8ch+kk+4);
// qi=32+g*4+kk: (extras(g,kk), 0)
__device__ u64      g_in2q[Bc * 48 * HWp];
__device__ u64      g_wt2q[5 * 9 * 36 * 128];   // conv w pairs [cid][tap][slot][oc]
__device__ u64      g_wtp2q[2 * 32 * 128];      // proj w pairs [s][slot][oc]
__device__ float    g_q   [Bc * CC * HWp];      // q conv output fp32
__device__ float    g_KV  [4 * Bc * CC * HWp];
__device__ u64      g_O2q [Bc * 2 * 32 * HWp];  // attn out, paired half2 planes

// ---------------- helpers ----------------
__device__ __forceinline__ unsigned smem_u32(const void* p) {
    return (unsigned)__cvta_generic_to_shared(p);
}
__device__ __forceinline__ void cp16(unsigned dst, const void* src, bool pred) {
    int sz = pred ? 16 : 0;
    asm volatile("cp.async.cg.shared.global [%0], [%1], 16, %2;\n"
                 :: "r"(dst), "l"(src), "r"(sz));
}
__device__ __forceinline__ void cp_commit() { asm volatile("cp.async.commit_group;\n"); }
template<int N> __device__ __forceinline__ void cp_wait() {
    asm volatile("cp.async.wait_group %0;\n" :: "n"(N));
}
__device__ __forceinline__ void mma_f16(float* c,
        unsigned a0, unsigned a1, unsigned a2, unsigned a3,
        unsigned b0, unsigned b1) {
    asm volatile("mma.sync.aligned.m16n8k16.row.col.f32.f16.f16.f32 "
                 "{%0,%1,%2,%3}, {%4,%5,%6,%7}, {%8,%9}, {%0,%1,%2,%3};\n"
                 : "+f"(c[0]), "+f"(c[1]), "+f"(c[2]), "+f"(c[3])
                 : "r"(a0), "r"(a1), "r"(a2), "r"(a3), "r"(b0), "r"(b1));
}
__device__ __forceinline__ unsigned packh2(float lo, float hi) {
    __half2 h = __floats2half2_rn(lo, hi);
    return *(unsigned*)&h;
}
__device__ __forceinline__ unsigned lo32(u64 v) { return (unsigned)v; }
__device__ __forceinline__ unsigned hi32(u64 v) { return (unsigned)(v >> 32); }
// ---- f32x2 helpers ----
__device__ __forceinline__ void ffma2(u64& acc, u64 a, u64 b) {
    asm("fma.rn.f32x2 %0, %1, %2, %0;" : "+l"(acc) : "l"(a), "l"(b));
}
__device__ __forceinline__ u64 mul2(u64 a, u64 b) {
    u64 r; asm("mul.rn.f32x2 %0, %1, %2;" : "=l"(r) : "l"(a), "l"(b));
    return r;
}
__device__ __forceinline__ u64 pack2f(float lo, float hi) {
    u64 r; asm("mov.b64 %0, {%1, %2};" : "=l"(r) : "f"(lo), "f"(hi));
    return r;
}
__device__ __forceinline__ u64 packdup(float v) {
    u64 r; asm("mov.b64 %0, {%1, %1};" : "=l"(r) : "f"(v));
    return r;
}
__device__ __forceinline__ void unpack2f(u64 p, float& lo, float& hi) {
    asm("mov.b64 {%0, %1}, %2;" : "=f"(lo), "=f"(hi) : "l"(p));
}

// ---------------- kernel: build paired half2 input planes ----------------
__global__ void build_in2q_kernel(const float* __restrict__ x,
                                  const float* __restrict__ ms,
                                  const float* __restrict__ lpan,
                                  const float* __restrict__ pan,
                                  const float* __restrict__ s)
{
    int idx = blockIdx.x * 256 + threadIdx.x;
    if (idx >= Bc * 48 * HWp) return;
    int p  = idx % HWp;
    int t  = idx / HWp;
    int qi = t % 48;
    int b  = t / 48;

    unsigned A, B;
    if (qi < 32) {
        int ch = qi >> 2, kk = qi & 3;
        int cpA = 8 * ch + kk;
        int cpB = cpA + 4;
        A = packh2(x[((size_t)b * CC + 2 * cpA)     * HWp + p],
                   x[((size_t)b * CC + 2 * cpA + 1) * HWp + p]);
        B = packh2(x[((size_t)b * CC + 2 * cpB)     * HWp + p],
                   x[((size_t)b * CC + 2 * cpB + 1) * HWp + p]);
    } else {
        int g = (qi - 32) >> 2;
        int e = qi & 3;
        float lp = lpan[b * HWp + p];
        float lo = 0.0f, hi = 0.0f;
        if (g == 0) {
            float sv = s[b];
            lo = lp * (1.0f - sv) + ms[(b * 8 + 2 * e)     * HWp + p] * sv;
            hi = lp * (1.0f - sv) + ms[(b * 8 + 2 * e + 1) * HWp + p] * sv;
        } else if (g == 1) {
            if (e == 0) lo = lp;
        } else if (g == 2) {
            if (e == 0)      { lo = lp; hi = pan[b * HWp + p]; }
            else if (e == 1) { lo = pan[b * HWp + p] - lp; }
        } else {
            lo = ms[(b * 8 + 2 * e)     * HWp + p];
            hi = ms[(b * 8 + 2 * e + 1) * HWp + p];
        }
        A = packh2(lo, hi);
        B = 0u;    // extras upper quad (e+4 >= 4) is zero for every group
    }
    g_in2q[idx] = (u64)A | ((u64)B << 32);
}

// ---------------- kernel: pack weights to paired half2 ----------------
__global__ void pack_w2q_kernel(const float* __restrict__ q_w,
                                const float* __restrict__ k_pan_w,
                                const float* __restrict__ v_pan_w,
                                const float* __restrict__ kv_ms_w,
                                const float* __restrict__ proj_pan_w,
                                const float* __restrict__ proj_ms_w)
{
    const int TOT_C = 5 * 9 * 36 * 128;
    int idx = blockIdx.x * 256 + threadIdx.x;
    if (idx < TOT_C) {
        int cid  = idx / (9 * 36 * 128);
        int rem  = idx % (9 * 36 * 128);
        int tap  = rem / (36 * 128);
        int rem2 = rem % (36 * 128);
        int slot = rem2 / 128;
        int oc   = rem2 % 128;
        int ch = slot >> 2, kk = slot & 3;
        int kpA = 8 * ch + kk, kpB = kpA + 4;
        const float* src; int cin;
        switch (cid) {
            case 0:  src = q_w;                      cin = 136; break;
            case 1:  src = k_pan_w;                  cin = 129; break;
            case 2:  src = v_pan_w;                  cin = 131; break;
            case 3:  src = kv_ms_w;                  cin = 136; break;
            default: src = kv_ms_w + 128 * 136 * 9;  cin = 136; break;
        }
        float la = (2 * kpA     < cin) ? src[((size_t)oc * cin + 2 * kpA)     * 9 + tap] : 0.0f;
        float ha = (2 * kpA + 1 < cin) ? src[((size_t)oc * cin + 2 * kpA + 1) * 9 + tap] : 0.0f;
        float lb = (2 * kpB     < cin) ? src[((size_t)oc * cin + 2 * kpB)     * 9 + tap] : 0.0f;
        float hb = (2 * kpB + 1 < cin) ? src[((size_t)oc * cin + 2 * kpB + 1) * 9 + tap] : 0.0f;
        g_wt2q[idx] = (u64)packh2(la, ha) | ((u64)packh2(lb, hb) << 32);
    } else {
        int r = idx - TOT_C;
        if (r >= 2 * 32 * 128) return;
        int sd   = r / (32 * 128);
        int slot = (r % (32 * 128)) / 128;
        int oc   = r % 128;
        int ch = slot >> 2, kk = slot & 3;
        int kpA = 8 * ch + kk, kpB = kpA + 4;
        const float* src = sd ? proj_ms_w : proj_pan_w;
        unsigned A = packh2(src[oc * 128 + 2 * kpA], src[oc * 128 + 2 * kpA + 1]);
        unsigned B = packh2(src[oc * 128 + 2 * kpB], src[oc * 128 + 2 * kpB + 1]);
        g_wtp2q[r] = (u64)A | ((u64)B << 32);
    }
}

// ---------------- fp16 mma conv kernel (u64-paired operands) ----------------
struct MCfg {
    const u64* inp;          // paired plane base
    long long inBStride;     // per-batch stride (u64 elements)
    int group;               // extras group (conv9)
    const u64* wt;           // [TAPS][SLOTS][128] u64 pairs
    const float* bias;
    float* out;
    long long outBStride;
    float scale;
};
struct MParams { MCfg c[5]; };

// block 512 thr = 16 warps (4M x 4N). M=128 oc, N=256 px (2 rows x 128 cols).
template<int TAPS, int HALO, int KPAIRS>
__global__ __launch_bounds__(512, 1)
void conv_mma_kernel(MParams P)
{
    constexpr int NCH     = KPAIRS / 8;
    constexpr int SLOTS   = KPAIRS / 2;
    constexpr int ROWS_ST = 2 + 2 * HALO;
    constexpr int COLS_ST = 128 + 8 * HALO;          // pixels (u64 each)
    constexpr int PSTR    = ROWS_ST * COLS_ST + 4;   // u64 plane stride; 2*PSTR % 32 == 8
    constexpr int OCS     = 132;                     // u64 oc stride;    2*OCS  % 32 == 8
    constexpr int COFF    = 3 * HALO;
    constexpr int VIN2    = COLS_ST / 2;
    constexpr int SIN_SZ  = 4 * PSTR;                // u64 per input buffer
    constexpr int SW_SZ   = TAPS * 4 * OCS;          // u64 per weight buffer
    constexpr int NIT_IN  = 4 * ROWS_ST * VIN2;
    constexpr int NIT_W   = TAPS * 4 * 64;

    extern __shared__ u64 smem64[];
    u64* sIn = smem64;                   // 2 buffers
    u64* sW  = smem64 + 2 * SIN_SZ;      // 2 buffers

    const int tid  = threadIdx.x;
    const int lane = tid & 31;
    const int wid  = tid >> 5;
    const int wm   = wid & 3;
    const int wn   = wid >> 2;
    const int r    = wn >> 1;
    const int cbase = (wn & 1) * 64;

    const int z   = blockIdx.z;
    const int b   = z % Bc;
    const MCfg cfg = P.c[z / Bc];
    const int ty0 = blockIdx.x * 2;

    const unsigned sInAddr = smem_u32(sIn);
    const unsigned sWAddr  = smem_u32(sW);

    float acc[2][8][4];
#pragma unroll
    for (int ti = 0; ti < 2; ti++)
#pragma unroll
        for (int j = 0; j < 8; j++)
#pragma unroll
            for (int q = 0; q < 4; q++) acc[ti][j][q] = 0.0f;

    const u64* inB = cfg.inp + (long long)b * cfg.inBStride;

    auto stage = [&](int ch, int bufsel) {
        const int qoff = (TAPS == 9) ? ((ch < 8) ? ch * 4 : 32 + cfg.group * 4)
                                     : ch * 4;
        unsigned dIn = sInAddr + (unsigned)bufsel * SIN_SZ * 8;
        for (int i = tid; i < NIT_IN; i += 512) {
            int kq  = i / (ROWS_ST * VIN2);
            int rem = i % (ROWS_ST * VIN2);
            int row = rem / VIN2;
            int v   = rem % VIN2;
            int gy  = ty0 + row - HALO;
            int gx  = 2 * v - 4 * HALO;
            const u64* src = inB + (long long)(qoff + kq) * HWp + gy * WW + gx;
            bool ok = (gy >= 0) && (gy < HH) && (gx >= 0) && (gx < WW);
            cp16(dIn + (unsigned)(kq * PSTR + row * COLS_ST + 2 * v) * 8, src, ok);
        }
        unsigned dW = sWAddr + (unsigned)bufsel * SW_SZ * 8;
        for (int i = tid; i < NIT_W; i += 512) {
            int tap = i >> 8;             // / 256
            int rem = i & 255;
            int kq  = rem >> 6;           // / 64
            int v   = rem & 63;
            const u64* src = cfg.wt + ((long long)tap * SLOTS + ch * 4 + kq) * 128 + 2 * v;
            cp16(dW + (unsigned)((tap * 4 + kq) * OCS + 2 * v) * 8, src, true);
        }
    };

    stage(0, 0);
    cp_commit();

    const int kk   = lane & 3;
    const int mrow = lane >> 2;
    const int ocA0 = wm * 32 + mrow;
    const int ib0  = kk * PSTR + r * COLS_ST + cbase + COFF + mrow;

    for (int ch = 0; ch < NCH; ch++) {
        if (ch + 1 < NCH) { stage(ch + 1, (ch + 1) & 1); cp_commit(); cp_wait<1>(); }
        else              { cp_wait<0>(); }
        __syncthreads();

        const u64* bufIn = sIn + (ch & 1) * SIN_SZ;
        const u64* bufW  = sW  + (ch & 1) * SW_SZ;

#pragma unroll
        for (int tap = 0; tap < TAPS; tap++) {
            const int dy = (TAPS == 9) ? tap / 3 : 0;
            const int dx = (TAPS == 9) ? tap % 3 : 0;

            const u64* wb = bufW + (tap * 4 + kk) * OCS;
            u64 A0 = wb[ocA0];          // (a0 | a2)
            u64 A1 = wb[ocA0 + 8];      // (a1 | a3)
            u64 C0 = wb[ocA0 + 16];
            u64 C1 = wb[ocA0 + 24];

            const u64* ibp = bufIn + ib0 + dy * COLS_ST + dx;
            u64 bb[8];
#pragma unroll
            for (int j = 0; j < 8; j++) bb[j] = ibp[j * 8];
#pragma unroll
            for (int j = 0; j < 8; j++) {
                mma_f16(acc[0][j], lo32(A0), lo32(A1), hi32(A0), hi32(A1),
                        lo32(bb[j]), hi32(bb[j]));
                mma_f16(acc[1][j], lo32(C0), lo32(C1), hi32(C0), hi32(C1),
                        lo32(bb[j]), hi32(bb[j]));
            }
        }
        __syncthreads();
    }

    float* outB = cfg.out + (long long)b * cfg.outBStride + (ty0 + r) * WW;
#pragma unroll
    for (int ti = 0; ti < 2; ti++) {
        int ocb = wm * 32 + ti * 16 + (lane >> 2);
        float b0 = cfg.bias[ocb];
        float b1 = cfg.bias[ocb + 8];
#pragma unroll
        for (int j = 0; j < 8; j++) {
            int col = cbase + j * 8 + (lane & 3) * 2;
            float* o0 = outB + (long long)ocb * HWp + col;
            float2 w0 = { (acc[ti][j][0] + b0) * cfg.scale,
                          (acc[ti][j][1] + b0) * cfg.scale };
            *(float2*)o0 = w0;
            float* o8 = o0 + 8 * HWp;
            float2 w1 = { (acc[ti][j][2] + b1) * cfg.scale,
                          (acc[ti][j][3] + b1) * cfg.scale };
            *(float2*)o8 = w1;
        }
    }
}

// ---------------- kernel: fused depthwise + attention (tiled, f32x2) -----
#define TLW 34
#define TLH 18
__global__ __launch_bounds__(256)
void attn_kernel(const float* __restrict__ q,
                 const float* __restrict__ KV,
                 const float* __restrict__ dw,
                 const float* __restrict__ db,
                 u64* __restrict__ O2q,
                 int sidx)
{
    __shared__ u64 sTile[8][TLH][TLW];
    __shared__ u64 sW2[8][9][9];
    __shared__ u64 sB2[8][9];

    const int tid = threadIdx.y * 32 + threadIdx.x;
    const int tx  = threadIdx.x;
    const int ty  = threadIdx.y;

    const int bn = blockIdx.x;
    const int b  = bn / NHh;
    const int n  = bn % NHh;
    const int s  = sidx;
    const int x0 = (blockIdx.y & 3) * 32;
    const int y0 = (blockIdx.y >> 2) * 16;

    for (int i = tid; i < 8 * 9 * 9; i += 256) {
        int dp = i / 81, a = (i / 9) % 9, t = i % 9;
        ((u64*)sW2)[i] = pack2f(dw[((2 * dp)     * 9 + a) * 9 + t],
                                dw[((2 * dp + 1) * 9 + a) * 9 + t]);
    }
    for (int i = tid; i < 72; i += 256) {
        int dp = i / 9, a = i % 9;
        ((u64*)sB2)[i] = pack2f(db[(2 * dp) * 9 + a], db[(2 * dp + 1) * 9 + a]);
    }

    const int py0 = y0 + 2 * ty;
    const int px  = x0 + tx;
    const int p0  = py0 * WW + px;
    const float* qB = q + ((size_t)b * CC + n * HDd) * HWp;

    auto loadTile = [&](const float* base) {
        for (int i = tid; i < 8 * TLH * TLW; i += 256) {
            int dp = i / (TLH * TLW);
            int rr = (i / TLW) % TLH;
            int cc = i % TLW;
            int gy = y0 + rr - 1, gx = x0 + cc - 1;
            float lo = 0.0f, hi = 0.0f;
            if (gy >= 0 && gy < HH && gx >= 0 && gx < WW) {
                const float* pl = base + (size_t)(2 * dp) * HWp + gy * WW + gx;
                lo = pl[0];
                hi = pl[HWp];
            }
            sTile[dp][rr][cc] = pack2f(lo, hi);
        }
    };

    const float* Kbase = KV + ((size_t)(2 * s)     * Bc + b) * CC * HWp + (size_t)(n * HDd) * HWp;
    const float* Vbase = KV + ((size_t)(2 * s + 1) * Bc + b) * CC * HWp + (size_t)(n * HDd) * HWp;

    // ---- K phase ----
    loadTile(Kbase);
    __syncthreads();

    u64 logits2[2][9];
#pragma unroll
    for (int j = 0; j < 2; j++)
#pragma unroll
        for (int a = 0; a < 9; a++) logits2[j][a] = 0ull;

    for (int dp = 0; dp < 8; dp++) {
        const float* qp = qB + (size_t)(2 * dp) * HWp + p0;
        u64 q2_0 = pack2f(qp[0],   qp[HWp]);
        u64 q2_1 = pack2f(qp[WW],  qp[HWp + WW]);
#pragma unroll
        for (int a = 0; a < 9; a++) {
            u64 b2 = sB2[dp][a];
            ffma2(logits2[0][a], q2_0, b2);
            ffma2(logits2[1][a], q2_1, b2);
        }
#pragma unroll
        for (int dx = 0; dx < 3; dx++) {
            u64 m0 = sTile[dp][2 * ty + 0][tx + dx];
            u64 m1 = sTile[dp][2 * ty + 1][tx + dx];
            u64 m2 = sTile[dp][2 * ty + 2][tx + dx];
            u64 m3 = sTile[dp][2 * ty + 3][tx + dx];
            u64 mq00 = mul2(q2_0, m0), mq01 = mul2(q2_0, m1), mq02 = mul2(q2_0, m2);
            u64 mq10 = mul2(q2_1, m1), mq11 = mul2(q2_1, m2), mq12 = mul2(q2_1, m3);
#pragma unroll
            for (int dy = 0; dy < 3; dy++) {
                int t = dy * 3 + dx;
                u64 a0 = (dy == 0) ? mq00 : (dy == 1) ? mq01 : mq02;
                u64 a1 = (dy == 0) ? mq10 : (dy == 1) ? mq11 : mq12;
#pragma unroll
                for (int a = 0; a < 9; a++) {
                    u64 w = sW2[dp][a][t];
                    ffma2(logits2[0][a], a0, w);
                    ffma2(logits2[1][a], a1, w);
                }
            }
        }
    }

    // ---- softmax ----
    u64 attn2[2][9];
#pragma unroll
    for (int j = 0; j < 2; j++) {
        float lg[9];
#pragma unroll
        for (int a = 0; a < 9; a++) {
            float lo, hi; unpack2f(logits2[j][a], lo, hi);
            lg[a] = lo + hi;
        }
        float m = lg[0];
#pragma unroll
        for (int a = 1; a < 9; a++) m = fmaxf(m, lg[a]);
        float sum = 0.0f;
#pragma unroll
        for (int a = 0; a < 9; a++) { lg[a] = __expf(lg[a] - m); sum += lg[a]; }
        float inv = 1.0f / sum;
#pragma unroll
        for (int a = 0; a < 9; a++) attn2[j][a] = packdup(lg[a] * inv);
    }

    // ---- V phase ----
    __syncthreads();
    loadTile(Vbase);
    __syncthreads();

    unsigned o0[8], o1[8];
    for (int dp = 0; dp < 8; dp++) {
        u64 m[4][3];
#pragma unroll
        for (int rr = 0; rr < 4; rr++)
#pragma unroll
            for (int cc = 0; cc < 3; cc++)
                m[rr][cc] = sTile[dp][2 * ty + rr][tx + cc];

        u64 out2_0 = 0ull, out2_1 = 0ull;
#pragma unroll
        for (int a = 0; a < 9; a++) {
            u64 b2 = sB2[dp][a];
            u64 v0 = b2, v1 = b2;
#pragma unroll
            for (int t = 0; t < 9; t++) {
                u64 w = sW2[dp][a][t];
                int dy = t / 3, dx = t % 3;
                ffma2(v0, m[dy][dx],     w);
                ffma2(v1, m[dy + 1][dx], w);
            }
            ffma2(out2_0, attn2[0][a], v0);
            ffma2(out2_1, attn2[1][a], v1);
        }
        float lo, hi;
        unpack2f(out2_0, lo, hi); o0[dp] = packh2(lo, hi);
        unpack2f(out2_1, lo, hi); o1[dp] = packh2(lo, hi);
    }

    // paired-u64 plane writes: qslot = n*4 + kk, word = (dp=kk | dp=kk+4)
    u64* oB = O2q + (((size_t)b * 2 + s) * 32 + n * 4) * HWp;
#pragma unroll
    for (int kk = 0; kk < 4; kk++) {
        oB[(size_t)kk * HWp + p0]      = (u64)o0[kk] | ((u64)o0[kk + 4] << 32);
        oB[(size_t)kk * HWp + p0 + WW] = (u64)o1[kk] | ((u64)o1[kk + 4] << 32);
    }
}

// ---------------- launch ----------------
extern "C" void kernel_launch(void* const* d_in, const int* in_sizes, int n_in,
                              void* d_out, int out_size)
{
    const float* x        = (const float*)d_in[0];
    const float* ms       = (const float*)d_in[1];
    const float* lpan     = (const float*)d_in[2];
    const float* pan      = (const float*)d_in[3];
    const float* s        = (const float*)d_in[4];
    const float* q_w      = (const float*)d_in[5];
    const float* q_b      = (const float*)d_in[6];
    const float* k_pan_w  = (const float*)d_in[7];
    const float* k_pan_b  = (const float*)d_in[8];
    const float* v_pan_w  = (const float*)d_in[9];
    const float* v_pan_b  = (const float*)d_in[10];
    const float* kv_ms_w  = (const float*)d_in[11];
    const float* kv_ms_b  = (const float*)d_in[12];
    const float* dep_w    = (const float*)d_in[13];
    const float* dep_b    = (const float*)d_in[14];
    const float* proj_pan_w = (const float*)d_in[15];
    const float* proj_pan_b = (const float*)d_in[16];
    const float* proj_ms_w  = (const float*)d_in[17];
    const float* proj_ms_b  = (const float*)d_in[18];

    u64 *gin2q, *gwt2q, *gwtp2q, *o2q;
    float *qb, *kv;
    cudaGetSymbolAddress((void**)&gin2q,  g_in2q);
    cudaGetSymbolAddress((void**)&gwt2q,  g_wt2q);
    cudaGetSymbolAddress((void**)&gwtp2q, g_wtp2q);
    cudaGetSymbolAddress((void**)&qb,     g_q);
    cudaGetSymbolAddress((void**)&kv,     g_KV);
    cudaGetSymbolAddress((void**)&o2q,    g_O2q);

    // smem (bytes): conv9: (2*4*548 + 2*9*4*132)*8 ; proj: (2*4*260 + 2*4*132)*8
    const int SMEM9 = (2 * 4 * 548 + 2 * 9 * 4 * 132) * 8;   // 111,104
    const int SMEM1 = (2 * 4 * 260 + 2 * 1 * 4 * 132) * 8;   //  25,088
    cudaFuncSetAttribute(conv_mma_kernel<9, 1, 72>,
                         cudaFuncAttributeMaxDynamicSharedMemorySize, SMEM9);
    cudaFuncSetAttribute(conv_mma_kernel<1, 0, 64>,
                         cudaFuncAttributeMaxDynamicSharedMemorySize, SMEM1);

    const long long STRM = (long long)Bc * CC * HWp;
    const long long INBS = 48LL * HWp;

    MParams PA = {};
    PA.c[0] = { gin2q, INBS, 0, gwt2q + 0LL * 9 * 36 * 128, q_b,
                qb,            (long long)CC * HWp, SCALEF };
    PA.c[1] = { gin2q, INBS, 1, gwt2q + 1LL * 9 * 36 * 128, k_pan_b,
                kv + 0 * STRM, (long long)CC * HWp, 1.0f };
    PA.c[2] = { gin2q, INBS, 2, gwt2q + 2LL * 9 * 36 * 128, v_pan_b,
                kv + 1 * STRM, (long long)CC * HWp, 1.0f };
    MParams PB = {};
    PB.c[0] = { gin2q, INBS, 3, gwt2q + 3LL * 9 * 36 * 128, kv_ms_b,
                kv + 2 * STRM, (long long)CC * HWp, 1.0f };
    PB.c[1] = { gin2q, INBS, 3, gwt2q + 4LL * 9 * 36 * 128, kv_ms_b + 128,
                kv + 3 * STRM, (long long)CC * HWp, 1.0f };

    float* dout = (float*)d_out;
    MParams PP = {};
    PP.c[0] = { o2q,             64LL * HWp, 0, gwtp2q,            proj_pan_b,
                dout,                            (long long)CC * HWp, 1.0f };
    PP.c[1] = { o2q + 32 * HWp,  64LL * HWp, 0, gwtp2q + 32 * 128, proj_ms_b,
                dout + (long long)Bc * CC * HWp, (long long)CC * HWp, 1.0f };

    const int nIn = Bc * 48 * HWp;
    const int nW  = 5 * 9 * 36 * 128 + 2 * 32 * 128;

    cudaStream_t sB = 0;
    cudaEvent_t evRoot = 0, evB = 0, evP = 0, evQ = 0, evM = 0;
    bool par = true;
    par = par && (cudaStreamCreateWithFlags(&sB, cudaStreamNonBlocking) == cudaSuccess);
    par = par && (cudaEventCreateWithFlags(&evRoot, cudaEventDisableTiming) == cudaSuccess);
    par = par && (cudaEventCreateWithFlags(&evB,    cudaEventDisableTiming) == cudaSuccess);
    par = par && (cudaEventCreateWithFlags(&evP,    cudaEventDisableTiming) == cudaSuccess);
    par = par && (cudaEventCreateWithFlags(&evQ,    cudaEventDisableTiming) == cudaSuccess);
    par = par && (cudaEventCreateWithFlags(&evM,    cudaEventDisableTiming) == cudaSuccess);

    if (par) {
        cudaEventRecord(evRoot, 0);
        cudaStreamWaitEvent(sB, evRoot, 0);

        build_in2q_kernel<<<(nIn + 255) / 256, 256, 0, 0>>>(x, ms, lpan, pan, s);
        cudaEventRecord(evB, 0);
        pack_w2q_kernel<<<(nW + 255) / 256, 256, 0, sB>>>(q_w, k_pan_w, v_pan_w, kv_ms_w,
                                                          proj_pan_w, proj_ms_w);
        cudaEventRecord(evP, sB);

        cudaStreamWaitEvent(0, evP, 0);
        conv_mma_kernel<9, 1, 72><<<dim3(64, 1, 3 * Bc), 512, SMEM9, 0>>>(PA);
        cudaEventRecord(evQ, 0);
        cudaStreamWaitEvent(sB, evB, 0);
        conv_mma_kernel<9, 1, 72><<<dim3(64, 1, 2 * Bc), 512, SMEM9, sB>>>(PB);

        attn_kernel<<<dim3(Bc * NHh, 32), dim3(32, 8), 0, 0>>>(qb, kv, dep_w, dep_b, o2q, 0);
        cudaStreamWaitEvent(sB, evQ, 0);
        attn_kernel<<<dim3(Bc * NHh, 32), dim3(32, 8), 0, sB>>>(qb, kv, dep_w, dep_b, o2q, 1);
        cudaEventRecord(evM, sB);

        cudaStreamWaitEvent(0, evM, 0);
        conv_mma_kernel<1, 0, 64><<<dim3(64, 1, 2 * Bc), 512, SMEM1, 0>>>(PP);
    } else {
        build_in2q_kernel<<<(nIn + 255) / 256, 256>>>(x, ms, lpan, pan, s);
        pack_w2q_kernel<<<(nW + 255) / 256, 256>>>(q_w, k_pan_w, v_pan_w, kv_ms_w,
                                                   proj_pan_w, proj_ms_w);
        conv_mma_kernel<9, 1, 72><<<dim3(64, 1, 3 * Bc), 512, SMEM9>>>(PA);
        conv_mma_kernel<9, 1, 72><<<dim3(64, 1, 2 * Bc), 512, SMEM9>>>(PB);
        attn_kernel<<<dim3(Bc * NHh, 32), dim3(32, 8)>>>(qb, kv, dep_w, dep_b, o2q, 0);
        attn_kernel<<<dim3(Bc * NHh, 32), dim3(32, 8)>>>(qb, kv, dep_w, dep_b, o2q, 1);
        conv_mma_kernel<1, 0, 64><<<dim3(64, 1, 2 * Bc), 512, SMEM1>>>(PP);
    }
}

// round 13
// speedup vs baseline: 1.1925x; 1.1925x over previous
#include <cuda_runtime.h>
#include <cuda_fp16.h>
#include <cstdint>

// ---------------- problem constants ----------------
#define Bc   2
#define CC   128
#define HH   128
#define WW   128
#define HWp  (HH*WW)
#define NHh  8
#define HDd  16
#define SCALEF 0.25f
#define NPLANES 96        // 64 x-pairs + 4 groups * 8 extras planes

typedef unsigned long long u64;

// ---------------- scratch ----------------
__device__ unsigned g_in2 [Bc * NPLANES * HWp];     // half2 channel-pair planes (conv input)
__device__ unsigned g_wt2 [5 * 9 * 72 * 128];       // conv weights half2 [cid][tap][kp][oc]
__device__ unsigned g_wtp2[2 * 64 * 128];           // proj weights half2 [s][kp][oc]
__device__ u64      g_q2  [Bc * 64 * HWp];          // q: fp32 pair-planes (d, d+8)
__device__ u64      g_KV2 [4 * Bc * 64 * HWp];      // K/V: fp32 pair-planes (d, d+8)
__device__ unsigned g_O2  [Bc * 2 * 64 * HWp];      // attn out, half2 pair-planes (d, d+8)

// ---------------- helpers ----------------
__device__ __forceinline__ unsigned smem_u32(const void* p) {
    return (unsigned)__cvta_generic_to_shared(p);
}
__device__ __forceinline__ void cp16(unsigned dst, const void* src, bool pred) {
    int sz = pred ? 16 : 0;
    asm volatile("cp.async.cg.shared.global [%0], [%1], 16, %2;\n"
                 :: "r"(dst), "l"(src), "r"(sz));
}
__device__ __forceinline__ void cp_commit() { asm volatile("cp.async.commit_group;\n"); }
template<int N> __device__ __forceinline__ void cp_wait() {
    asm volatile("cp.async.wait_group %0;\n" :: "n"(N));
}
__device__ __forceinline__ void mma_f16(float* c,
        unsigned a0, unsigned a1, unsigned a2, unsigned a3,
        unsigned b0, unsigned b1) {
    asm volatile("mma.sync.aligned.m16n8k16.row.col.f32.f16.f16.f32 "
                 "{%0,%1,%2,%3}, {%4,%5,%6,%7}, {%8,%9}, {%0,%1,%2,%3};\n"
                 : "+f"(c[0]), "+f"(c[1]), "+f"(c[2]), "+f"(c[3])
                 : "r"(a0), "r"(a1), "r"(a2), "r"(a3), "r"(b0), "r"(b1));
}
__device__ __forceinline__ unsigned packh2(float lo, float hi) {
    __half2 h = __floats2half2_rn(lo, hi);
    return *(unsigned*)&h;
}
// ---- f32x2 helpers ----
__device__ __forceinline__ void ffma2(u64& acc, u64 a, u64 b) {
    asm("fma.rn.f32x2 %0, %1, %2, %0;" : "+l"(acc) : "l"(a), "l"(b));
}
__device__ __forceinline__ u64 mul2(u64 a, u64 b) {
    u64 r; asm("mul.rn.f32x2 %0, %1, %2;" : "=l"(r) : "l"(a), "l"(b));
    return r;
}
__device__ __forceinline__ u64 pack2f(float lo, float hi) {
    u64 r; asm("mov.b64 %0, {%1, %2};" : "=l"(r) : "f"(lo), "f"(hi));
    return r;
}
__device__ __forceinline__ u64 packdup(float v) {
    u64 r; asm("mov.b64 %0, {%1, %1};" : "=l"(r) : "f"(v));
    return r;
}
__device__ __forceinline__ void unpack2f(u64 p, float& lo, float& hi) {
    asm("mov.b64 {%0, %1}, %2;" : "=f"(lo), "=f"(hi) : "l"(p));
}

// ---------------- kernel: build half2 input planes (R10 layout) ----------------
__global__ void build_in2_kernel(const float* __restrict__ x,
                                 const float* __restrict__ ms,
                                 const float* __restrict__ lpan,
                                 const float* __restrict__ pan,
                                 const float* __restrict__ s)
{
    int idx = blockIdx.x * 256 + threadIdx.x;
    if (idx >= Bc * NPLANES * HWp) return;
    int p  = idx % HWp;
    int t  = idx / HWp;
    int pl = t % NPLANES;
    int b  = t / NPLANES;
    float lo = 0.0f, hi = 0.0f;
    if (pl < 64) {
        lo = x[((size_t)b * CC + 2 * pl)     * HWp + p];
        hi = x[((size_t)b * CC + 2 * pl + 1) * HWp + p];
    } else {
        int g = (pl - 64) >> 3;
        int e = (pl - 64) & 7;
        float lp = lpan[b * HWp + p];
        if (g == 0) {
            if (e < 4) {
                float sv = s[b];
                lo = lp * (1.0f - sv) + ms[(b * 8 + 2 * e)     * HWp + p] * sv;
                hi = lp * (1.0f - sv) + ms[(b * 8 + 2 * e + 1) * HWp + p] * sv;
            }
        } else if (g == 1) {
            if (e == 0) lo = lp;
        } else if (g == 2) {
            if (e == 0)      { lo = lp; hi = pan[b * HWp + p]; }
            else if (e == 1) { lo = pan[b * HWp + p] - lp; }
        } else {
            if (e < 4) {
                lo = ms[(b * 8 + 2 * e)     * HWp + p];
                hi = ms[(b * 8 + 2 * e + 1) * HWp + p];
            }
        }
    }
    g_in2[idx] = packh2(lo, hi);
}

// ---------------- kernel: pack weights to half2 ----------------
// conv weights: pairing (2kp, 2kp+1) over input channels (unchanged).
// proj weights: K-pairing follows attn-out pair-planes: kp -> (n*16+dp, n*16+dp+8).
__global__ void pack_w2_kernel(const float* __restrict__ q_w,
                               const float* __restrict__ k_pan_w,
                               const float* __restrict__ v_pan_w,
                               const float* __restrict__ kv_ms_w,
                               const float* __restrict__ proj_pan_w,
                               const float* __restrict__ proj_ms_w)
{
    const int TOT_C = 5 * 9 * 72 * 128;
    int idx = blockIdx.x * 256 + threadIdx.x;
    if (idx < TOT_C) {
        int cid  = idx / (9 * 72 * 128);
        int rem  = idx % (9 * 72 * 128);
        int tap  = rem / (72 * 128);
        int rem2 = rem % (72 * 128);
        int kp   = rem2 / 128;
        int oc   = rem2 % 128;
        const float* src; int cin;
        switch (cid) {
            case 0:  src = q_w;                      cin = 136; break;
            case 1:  src = k_pan_w;                  cin = 129; break;
            case 2:  src = v_pan_w;                  cin = 131; break;
            case 3:  src = kv_ms_w;                  cin = 136; break;
            default: src = kv_ms_w + 128 * 136 * 9;  cin = 136; break;
        }
        int k0 = 2 * kp, k1 = 2 * kp + 1;
        float lo = (k0 < cin) ? src[((size_t)oc * cin + k0) * 9 + tap] : 0.0f;
        float hi = (k1 < cin) ? src[((size_t)oc * cin + k1) * 9 + tap] : 0.0f;
        g_wt2[idx] = packh2(lo, hi);
    } else {
        int r = idx - TOT_C;
        if (r >= 2 * 64 * 128) return;
        int sd = r / (64 * 128);
        int kp = (r % (64 * 128)) / 128;
        int oc = r % 128;
        int n  = kp >> 3, dp = kp & 7;
        int k0 = n * 16 + dp, k1 = k0 + 8;     // (d, d+8) pair within head
        const float* src = sd ? proj_ms_w : proj_pan_w;
        g_wtp2[r] = packh2(src[oc * 128 + k0], src[oc * 128 + k1]);
    }
}

// ---------------- fp16 mma conv kernel (R10 mainloop; paired epilogue for TAPS=9) ----
struct MCfg {
    const unsigned* inp;     // half2 plane base
    long long inBStride;     // per-batch stride (half2 elements)
    int group;               // extras-plane group (conv9)
    const unsigned* wt;      // [TAPS][KPAIRS][128] half2
    const float* bias;
    float* out;              // TAPS==9: float2 pair-plane base; TAPS==1: planar fp32
    long long outBStride;    // TAPS==9: float2 units; TAPS==1: float units
    float scale;
};
struct MParams { MCfg c[5]; };

template<int TAPS, int HALO, int KPAIRS>
__global__ __launch_bounds__(512, 1)
void conv_mma_kernel(MParams P)
{
    constexpr int NCH     = KPAIRS / 8;
    constexpr int ROWS_ST = 2 + 2 * HALO;
    constexpr int COLS_ST = 128 + 8 * HALO;
    constexpr int PSTR    = ROWS_ST * COLS_ST + 8;
    constexpr int OCSTR   = 136;
    constexpr int COFF    = 3 * HALO;
    constexpr int VIN     = COLS_ST / 4;
    constexpr int SIN_SZ  = 8 * PSTR;
    constexpr int SW_SZ   = TAPS * 8 * OCSTR;
    constexpr int NIT_IN  = 8 * ROWS_ST * VIN;
    constexpr int NIT_W   = TAPS * 8 * 32;

    extern __shared__ unsigned smem[];
    unsigned* sIn = smem;
    unsigned* sW  = smem + 2 * SIN_SZ;

    const int tid  = threadIdx.x;
    const int lane = tid & 31;
    const int wid  = tid >> 5;
    const int wm   = wid & 3;
    const int wn   = wid >> 2;
    const int r    = wn >> 1;
    const int cbase = (wn & 1) * 64;

    const int z   = blockIdx.z;
    const int b   = z % Bc;
    const MCfg cfg = P.c[z / Bc];
    const int ty0 = blockIdx.x * 2;

    const unsigned sInAddr = smem_u32(sIn);
    const unsigned sWAddr  = smem_u32(sW);

    float acc[2][8][4];
#pragma unroll
    for (int ti = 0; ti < 2; ti++)
#pragma unroll
        for (int j = 0; j < 8; j++)
#pragma unroll
            for (int q = 0; q < 4; q++) acc[ti][j][q] = 0.0f;

    const unsigned* inB = cfg.inp + (long long)b * cfg.inBStride;

    auto stage = [&](int ch, int bufsel) {
        const int c0 = ch * 8;
        unsigned dIn = sInAddr + (unsigned)bufsel * SIN_SZ * 4;
        for (int i = tid; i < NIT_IN; i += 512) {
            int ci  = i / (ROWS_ST * VIN);
            int rem = i % (ROWS_ST * VIN);
            int row = rem / VIN;
            int v   = rem % VIN;
            int gy  = ty0 + row - HALO;
            int gx  = 4 * v - 4 * HALO;
            int cp  = c0 + ci;
            int pl  = (cp < 64) ? cp : (64 + cfg.group * 8 + (cp - 64));
            const unsigned* src = inB + (long long)pl * HWp + gy * WW + gx;
            bool ok = (gy >= 0) && (gy < HH) && (gx >= 0) && (gx < WW);
            cp16(dIn + (unsigned)(ci * PSTR + row * COLS_ST + 4 * v) * 4, src, ok);
        }
        unsigned dW = sWAddr + (unsigned)bufsel * SW_SZ * 4;
        for (int i = tid; i < NIT_W; i += 512) {
            int tap = i >> 8;
            int rem = i & 255;
            int k   = rem >> 5;
            int v   = rem & 31;
            const unsigned* src = cfg.wt + ((long long)tap * KPAIRS + (c0 + k)) * 128 + 4 * v;
            cp16(dW + (unsigned)((tap * 8 + k) * OCSTR + 4 * v) * 4, src, true);
        }
    };

    stage(0, 0);
    cp_commit();

    const int kk   = lane & 3;
    const int mrow = lane >> 2;
    const int ocA0 = wm * 32 + mrow;
    const int ib0  = kk * PSTR + r * COLS_ST + cbase + COFF + (lane >> 2);

    for (int ch = 0; ch < NCH; ch++) {
        if (ch + 1 < NCH) { stage(ch + 1, (ch + 1) & 1); cp_commit(); cp_wait<1>(); }
        else              { cp_wait<0>(); }
        __syncthreads();

        const unsigned* bufIn = sIn + (ch & 1) * SIN_SZ;
        const unsigned* bufW  = sW  + (ch & 1) * SW_SZ;

#pragma unroll
        for (int tap = 0; tap < TAPS; tap++) {
            const int dy = (TAPS == 9) ? tap / 3 : 0;
            const int dx = (TAPS == 9) ? tap % 3 : 0;

            const unsigned* wb = bufW + tap * 8 * OCSTR + kk * OCSTR;
            unsigned a0 = wb[ocA0];
            unsigned a1 = wb[ocA0 + 8];
            unsigned a2 = wb[4 * OCSTR + ocA0];
            unsigned a3 = wb[4 * OCSTR + ocA0 + 8];
            unsigned c0_ = wb[ocA0 + 16];
            unsigned c1_ = wb[ocA0 + 24];
            unsigned c2_ = wb[4 * OCSTR + ocA0 + 16];
            unsigned c3_ = wb[4 * OCSTR + ocA0 + 24];

            const unsigned* ibp = bufIn + ib0 + dy * COLS_ST + dx;
            unsigned bf[8][2];
#pragma unroll
            for (int j = 0; j < 8; j++) {
                bf[j][0] = ibp[j * 8];
                bf[j][1] = ibp[4 * PSTR + j * 8];
            }
#pragma unroll
            for (int j = 0; j < 8; j++) {
                mma_f16(acc[0][j], a0, a1, a2, a3, bf[j][0], bf[j][1]);
                mma_f16(acc[1][j], c0_, c1_, c2_, c3_, bf[j][0], bf[j][1]);
            }
        }
        __syncthreads();
    }

    // ---- epilogue ----
    if (TAPS == 9) {
        // paired float2 pair-planes: plane = head*8 + mrow, pair = (oc, oc+8)
        const int mr = lane >> 2;
#pragma unroll
        for (int ti = 0; ti < 2; ti++) {
            int head = 2 * wm + ti;
            int oc   = head * 16 + mr;
            float b0 = cfg.bias[oc];
            float b1 = cfg.bias[oc + 8];
            float2* po = (float2*)cfg.out + (long long)b * cfg.outBStride
                       + (long long)(head * 8 + mr) * HWp + (ty0 + r) * WW;
#pragma unroll
            for (int j = 0; j < 8; j++) {
                int col = cbase + j * 8 + (lane & 3) * 2;
                float4 v = { (acc[ti][j][0] + b0) * cfg.scale,
                             (acc[ti][j][2] + b1) * cfg.scale,
                             (acc[ti][j][1] + b0) * cfg.scale,
                             (acc[ti][j][3] + b1) * cfg.scale };
                *(float4*)(po + col) = v;
            }
        }
    } else {
        float* outB = cfg.out + (long long)b * cfg.outBStride + (ty0 + r) * WW;
#pragma unroll
        for (int ti = 0; ti < 2; ti++) {
            int ocb = wm * 32 + ti * 16 + (lane >> 2);
            float b0 = cfg.bias[ocb];
            float b1 = cfg.bias[ocb + 8];
#pragma unroll
            for (int j = 0; j < 8; j++) {
                int col = cbase + j * 8 + (lane & 3) * 2;
                float* o0 = outB + (long long)ocb * HWp + col;
                float2 w0 = { (acc[ti][j][0] + b0) * cfg.scale,
                              (acc[ti][j][1] + b0) * cfg.scale };
                *(float2*)o0 = w0;
                float* o8 = o0 + 8 * HWp;
                float2 w1 = { (acc[ti][j][2] + b1) * cfg.scale,
                              (acc[ti][j][3] + b1) * cfg.scale };
                *(float2*)o8 = w1;
            }
        }
    }
}

// ---------------- kernel: fused depthwise + attention (pair-plane I/O) -----
#define TLW 34
#define TLH 18
__global__ __launch_bounds__(256)
void attn_kernel(const u64* __restrict__ q2,
                 const u64* __restrict__ KV2,
                 const float* __restrict__ dw,
                 const float* __restrict__ db,
                 unsigned* __restrict__ O2,
                 int sidx)
{
    __shared__ u64 sTile[8][TLH][TLW];
    __shared__ u64 sW2[8][9][9];
    __shared__ u64 sB2[8][9];

    const int tid = threadIdx.y * 32 + threadIdx.x;
    const int tx  = threadIdx.x;
    const int ty  = threadIdx.y;

    const int bn = blockIdx.x;
    const int b  = bn / NHh;
    const int n  = bn % NHh;
    const int s  = sidx;
    const int x0 = (blockIdx.y & 3) * 32;
    const int y0 = (blockIdx.y >> 2) * 16;

    // weights paired (d, d+8)
    for (int i = tid; i < 8 * 9 * 9; i += 256) {
        int dp = i / 81, a = (i / 9) % 9, t = i % 9;
        ((u64*)sW2)[i] = pack2f(dw[(dp * 9 + a) * 9 + t],
                                dw[((dp + 8) * 9 + a) * 9 + t]);
    }
    for (int i = tid; i < 72; i += 256) {
        int dp = i / 9, a = i % 9;
        ((u64*)sB2)[i] = pack2f(db[dp * 9 + a], db[(dp + 8) * 9 + a]);
    }

    const int py0 = y0 + 2 * ty;
    const int px  = x0 + tx;
    const int p0  = py0 * WW + px;
    const u64* qB = q2 + ((size_t)b * 64 + n * 8) * HWp;

    // tile loader: one LDG.64 per texel (fp32 pair)
    auto loadTile = [&](const u64* base) {
        for (int i = tid; i < 8 * TLH * TLW; i += 256) {
            int dp = i / (TLH * TLW);
            int rr = (i / TLW) % TLH;
            int cc = i % TLW;
            int gy = y0 + rr - 1, gx = x0 + cc - 1;
            u64 v = 0ull;
            if (gy >= 0 && gy < HH && gx >= 0 && gx < WW)
                v = base[(size_t)dp * HWp + gy * WW + gx];
            sTile[dp][rr][cc] = v;
        }
    };

    const u64* Kbase = KV2 + (((size_t)(2 * s)     * Bc + b) * 64 + n * 8) * HWp;
    const u64* Vbase = KV2 + (((size_t)(2 * s + 1) * Bc + b) * 64 + n * 8) * HWp;

    // ---- K phase ----
    loadTile(Kbase);
    __syncthreads();

    u64 logits2[2][9];
#pragma unroll
    for (int j = 0; j < 2; j++)
#pragma unroll
        for (int a = 0; a < 9; a++) logits2[j][a] = 0ull;

    for (int dp = 0; dp < 8; dp++) {
        const u64* qp = qB + (size_t)dp * HWp + p0;
        u64 q2_0 = qp[0];
        u64 q2_1 = qp[WW];
#pragma unroll
        for (int a = 0; a < 9; a++) {
            u64 b2 = sB2[dp][a];
            ffma2(logits2[0][a], q2_0, b2);
            ffma2(logits2[1][a], q2_1, b2);
        }
#pragma unroll
        for (int dx = 0; dx < 3; dx++) {
            u64 m0 = sTile[dp][2 * ty + 0][tx + dx];
            u64 m1 = sTile[dp][2 * ty + 1][tx + dx];
            u64 m2 = sTile[dp][2 * ty + 2][tx + dx];
            u64 m3 = sTile[dp][2 * ty + 3][tx + dx];
            u64 mq00 = mul2(q2_0, m0), mq01 = mul2(q2_0, m1), mq02 = mul2(q2_0, m2);
            u64 mq10 = mul2(q2_1, m1), mq11 = mul2(q2_1, m2), mq12 = mul2(q2_1, m3);
#pragma unroll
            for (int dy = 0; dy < 3; dy++) {
                int t = dy * 3 + dx;
                u64 a0 = (dy == 0) ? mq00 : (dy == 1) ? mq01 : mq02;
                u64 a1 = (dy == 0) ? mq10 : (dy == 1) ? mq11 : mq12;
#pragma unroll
                for (int a = 0; a < 9; a++) {
                    u64 w = sW2[dp][a][t];
                    ffma2(logits2[0][a], a0, w);
                    ffma2(logits2[1][a], a1, w);
                }
            }
        }
    }

    // ---- softmax ----
    u64 attn2[2][9];
#pragma unroll
    for (int j = 0; j < 2; j++) {
        float lg[9];
#pragma unroll
        for (int a = 0; a < 9; a++) {
            float lo, hi; unpack2f(logits2[j][a], lo, hi);
            lg[a] = lo + hi;
        }
        float m = lg[0];
#pragma unroll
        for (int a = 1; a < 9; a++) m = fmaxf(m, lg[a]);
        float sum = 0.0f;
#pragma unroll
        for (int a = 0; a < 9; a++) { lg[a] = __expf(lg[a] - m); sum += lg[a]; }
        float inv = 1.0f / sum;
#pragma unroll
        for (int a = 0; a < 9; a++) attn2[j][a] = packdup(lg[a] * inv);
    }

    // ---- V phase ----
    __syncthreads();
    loadTile(Vbase);
    __syncthreads();

    for (int dp = 0; dp < 8; dp++) {
        u64 m[4][3];
#pragma unroll
        for (int rr = 0; rr < 4; rr++)
#pragma unroll
            for (int cc = 0; cc < 3; cc++)
                m[rr][cc] = sTile[dp][2 * ty + rr][tx + cc];

        u64 out2_0 = 0ull, out2_1 = 0ull;
#pragma unroll
        for (int a = 0; a < 9; a++) {
            u64 b2 = sB2[dp][a];
            u64 v0 = b2, v1 = b2;
#pragma unroll
            for (int t = 0; t < 9; t++) {
                u64 w = sW2[dp][a][t];
                int dy = t / 3, dx = t % 3;
                ffma2(v0, m[dy][dx],     w);
                ffma2(v1, m[dy + 1][dx], w);
            }
            ffma2(out2_0, attn2[0][a], v0);
            ffma2(out2_1, attn2[1][a], v1);
        }

        // O2 plane (b*2+s)*64 + n*8 + dp holds half2(out[d], out[d+8])
        float lo, hi;
        unsigned* oB = O2 + (((size_t)b * 2 + s) * 64 + n * 8 + dp) * HWp;
        unpack2f(out2_0, lo, hi);
        oB[p0] = packh2(lo, hi);
        unpack2f(out2_1, lo, hi);
        oB[p0 + WW] = packh2(lo, hi);
    }
}

// ---------------- launch ----------------
extern "C" void kernel_launch(void* const* d_in, const int* in_sizes, int n_in,
                              void* d_out, int out_size)
{
    const float* x        = (const float*)d_in[0];
    const float* ms       = (const float*)d_in[1];
    const float* lpan     = (const float*)d_in[2];
    const float* pan      = (const float*)d_in[3];
    const float* s        = (const float*)d_in[4];
    const float* q_w      = (const float*)d_in[5];
    const float* q_b      = (const float*)d_in[6];
    const float* k_pan_w  = (const float*)d_in[7];
    const float* k_pan_b  = (const float*)d_in[8];
    const float* v_pan_w  = (const float*)d_in[9];
    const float* v_pan_b  = (const float*)d_in[10];
    const float* kv_ms_w  = (const float*)d_in[11];
    const float* kv_ms_b  = (const float*)d_in[12];
    const float* dep_w    = (const float*)d_in[13];
    const float* dep_b    = (const float*)d_in[14];
    const float* proj_pan_w = (const float*)d_in[15];
    const float* proj_pan_b = (const float*)d_in[16];
    const float* proj_ms_w  = (const float*)d_in[17];
    const float* proj_ms_b  = (const float*)d_in[18];

    unsigned *gin2, *gwt2, *gwtp2, *o2;
    u64 *q2, *kv2;
    cudaGetSymbolAddress((void**)&gin2,  g_in2);
    cudaGetSymbolAddress((void**)&gwt2,  g_wt2);
    cudaGetSymbolAddress((void**)&gwtp2, g_wtp2);
    cudaGetSymbolAddress((void**)&q2,    g_q2);
    cudaGetSymbolAddress((void**)&kv2,   g_KV2);
    cudaGetSymbolAddress((void**)&o2,    g_O2);

    const int SMEM9 = (2 * (8 * (4 * 136 + 8)) + 2 * (9 * 8 * 136)) * 4;
    const int SMEM1 = (2 * (8 * (2 * 128 + 8)) + 2 * (1 * 8 * 136)) * 4;
    cudaFuncSetAttribute(conv_mma_kernel<9, 1, 72>,
                         cudaFuncAttributeMaxDynamicSharedMemorySize, SMEM9);
    cudaFuncSetAttribute(conv_mma_kernel<1, 0, 64>,
                         cudaFuncAttributeMaxDynamicSharedMemorySize, SMEM1);

    const long long INBS  = (long long)NPLANES * HWp;   // conv input batch stride (half2)
    const long long PSTRM = 64LL * Bc * HWp;            // one KV stream-part (float2 units... per part = Bc*64*HWp)

    // stream-A convs: q, k_pan, v_pan (paired float2 outputs)
    MParams PA = {};
    PA.c[0] = { gin2, INBS, 0, gwt2 + 0LL * 9 * 72 * 128, q_b,
                (float*)q2,                 64LL * HWp, SCALEF };
    PA.c[1] = { gin2, INBS, 1, gwt2 + 1LL * 9 * 72 * 128, k_pan_b,
                (float*)(kv2 + 0LL * PSTRM), 64LL * HWp, 1.0f };
    PA.c[2] = { gin2, INBS, 2, gwt2 + 2LL * 9 * 72 * 128, v_pan_b,
                (float*)(kv2 + 1LL * PSTRM), 64LL * HWp, 1.0f };
    // stream-B convs: kv_ms halves
    MParams PB = {};
    PB.c[0] = { gin2, INBS, 3, gwt2 + 3LL * 9 * 72 * 128, kv_ms_b,
                (float*)(kv2 + 2LL * PSTRM), 64LL * HWp, 1.0f };
    PB.c[1] = { gin2, INBS, 3, gwt2 + 4LL * 9 * 72 * 128, kv_ms_b + 128,
                (float*)(kv2 + 3LL * PSTRM), 64LL * HWp, 1.0f };

    // projection (planar fp32 output to d_out)
    float* dout = (float*)d_out;
    MParams PP = {};
    PP.c[0] = { o2,            2LL * 64 * HWp, 0, gwtp2,            proj_pan_b,
                dout,                            (long long)CC * HWp, 1.0f };
    PP.c[1] = { o2 + 64 * HWp, 2LL * 64 * HWp, 0, gwtp2 + 64 * 128, proj_ms_b,
                dout + (long long)Bc * CC * HWp, (long long)CC * HWp, 1.0f };

    const int nIn = Bc * NPLANES * HWp;
    const int nW  = 5 * 9 * 72 * 128 + 2 * 64 * 128;

    cudaStream_t sB = 0;
    cudaEvent_t evRoot = 0, evB = 0, evP = 0, evQ = 0, evM = 0;
    bool par = true;
    par = par && (cudaStreamCreateWithFlags(&sB, cudaStreamNonBlocking) == cudaSuccess);
    par = par && (cudaEventCreateWithFlags(&evRoot, cudaEventDisableTiming) == cudaSuccess);
    par = par && (cudaEventCreateWithFlags(&evB,    cudaEventDisableTiming) == cudaSuccess);
    par = par && (cudaEventCreateWithFlags(&evP,    cudaEventDisableTiming) == cudaSuccess);
    par = par && (cudaEventCreateWithFlags(&evQ,    cudaEventDisableTiming) == cudaSuccess);
    par = par && (cudaEventCreateWithFlags(&evM,    cudaEventDisableTiming) == cudaSuccess);

    if (par) {
        cudaEventRecord(evRoot, 0);
        cudaStreamWaitEvent(sB, evRoot, 0);

        build_in2_kernel<<<(nIn + 255) / 256, 256, 0, 0>>>(x, ms, lpan, pan, s);
        cudaEventRecord(evB, 0);
        pack_w2_kernel<<<(nW + 255) / 256, 256, 0, sB>>>(q_w, k_pan_w, v_pan_w, kv_ms_w,
                                                         proj_pan_w, proj_ms_w);
        cudaEventRecord(evP, sB);

        cudaStreamWaitEvent(0, evP, 0);
        conv_mma_kernel<9, 1, 72><<<dim3(64, 1, 3 * Bc), 512, SMEM9, 0>>>(PA);
        cudaEventRecord(evQ, 0);
        cudaStreamWaitEvent(sB, evB, 0);
        conv_mma_kernel<9, 1, 72><<<dim3(64, 1, 2 * Bc), 512, SMEM9, sB>>>(PB);

        attn_kernel<<<dim3(Bc * NHh, 32), dim3(32, 8), 0, 0>>>(q2, kv2, dep_w, dep_b, o2, 0);
        cudaStreamWaitEvent(sB, evQ, 0);
        attn_kernel<<<dim3(Bc * NHh, 32), dim3(32, 8), 0, sB>>>(q2, kv2, dep_w, dep_b, o2, 1);
        cudaEventRecord(evM, sB);

        cudaStreamWaitEvent(0, evM, 0);
        conv_mma_kernel<1, 0, 64><<<dim3(64, 1, 2 * Bc), 512, SMEM1, 0>>>(PP);
    } else {
        build_in2_kernel<<<(nIn + 255) / 256, 256>>>(x, ms, lpan, pan, s);
        pack_w2_kernel<<<(nW + 255) / 256, 256>>>(q_w, k_pan_w, v_pan_w, kv_ms_w,
                                                  proj_pan_w, proj_ms_w);
        conv_mma_kernel<9, 1, 72><<<dim3(64, 1, 3 * Bc), 512, SMEM9>>>(PA);
        conv_mma_kernel<9, 1, 72><<<dim3(64, 1, 2 * Bc), 512, SMEM9>>>(PB);
        attn_kernel<<<dim3(Bc * NHh, 32), dim3(32, 8)>>>(q2, kv2, dep_w, dep_b, o2, 0);
        attn_kernel<<<dim3(Bc * NHh, 32), dim3(32, 8)>>>(q2, kv2, dep_w, dep_b, o2, 1);
        conv_mma_kernel<1, 0, 64><<<dim3(64, 1, 2 * Bc), 512, SMEM1>>>(PP);
    }
}

// round 14
// speedup vs baseline: 1.2710x; 1.0659x over previous
#include <cuda_runtime.h>
#include <cuda_fp16.h>
#include <cstdint>

// ---------------- problem constants ----------------
#define Bc   2
#define CC   128
#define HH   128
#define WW   128
#define HWp  (HH*WW)
#define NHh  8
#define HDd  16
#define SCALEF 0.25f
#define NPLANES 96        // 64 x-pairs + 4 groups * 8 extras planes

typedef unsigned long long u64;

// ---------------- scratch ----------------
__device__ unsigned g_in2 [Bc * NPLANES * HWp];     // half2 channel-pair planes (conv input)
__device__ unsigned g_wt2 [5 * 9 * 72 * 128];       // conv weights half2 [cid][tap][kp][oc]
__device__ unsigned g_wtp2[2 * 64 * 128];           // proj weights half2 [s][kp][oc]
__device__ u64      g_q2  [Bc * 64 * HWp];          // q: fp32 pair-planes (d, d+8)
__device__ u64      g_KV2 [4 * Bc * 64 * HWp];      // K/V: fp32 pair-planes (d, d+8)
__device__ unsigned g_O2  [Bc * 2 * 64 * HWp];      // attn out, half2 pair-planes (d, d+8)

// ---------------- helpers ----------------
__device__ __forceinline__ unsigned smem_u32(const void* p) {
    return (unsigned)__cvta_generic_to_shared(p);
}
__device__ __forceinline__ void cp16(unsigned dst, const void* src, bool pred) {
    int sz = pred ? 16 : 0;
    asm volatile("cp.async.cg.shared.global [%0], [%1], 16, %2;\n"
                 :: "r"(dst), "l"(src), "r"(sz));
}
__device__ __forceinline__ void cp_commit() { asm volatile("cp.async.commit_group;\n"); }
template<int N> __device__ __forceinline__ void cp_wait() {
    asm volatile("cp.async.wait_group %0;\n" :: "n"(N));
}
__device__ __forceinline__ void mma_f16(float* c,
        unsigned a0, unsigned a1, unsigned a2, unsigned a3,
        unsigned b0, unsigned b1) {
    asm volatile("mma.sync.aligned.m16n8k16.row.col.f32.f16.f16.f32 "
                 "{%0,%1,%2,%3}, {%4,%5,%6,%7}, {%8,%9}, {%0,%1,%2,%3};\n"
                 : "+f"(c[0]), "+f"(c[1]), "+f"(c[2]), "+f"(c[3])
                 : "r"(a0), "r"(a1), "r"(a2), "r"(a3), "r"(b0), "r"(b1));
}
__device__ __forceinline__ unsigned packh2(float lo, float hi) {
    __half2 h = __floats2half2_rn(lo, hi);
    return *(unsigned*)&h;
}
// ---- f32x2 helpers ----
__device__ __forceinline__ void ffma2(u64& acc, u64 a, u64 b) {
    asm("fma.rn.f32x2 %0, %1, %2, %0;" : "+l"(acc) : "l"(a), "l"(b));
}
__device__ __forceinline__ u64 mul2(u64 a, u64 b) {
    u64 r; asm("mul.rn.f32x2 %0, %1, %2;" : "=l"(r) : "l"(a), "l"(b));
    return r;
}
__device__ __forceinline__ u64 pack2f(float lo, float hi) {
    u64 r; asm("mov.b64 %0, {%1, %2};" : "=l"(r) : "f"(lo), "f"(hi));
    return r;
}
__device__ __forceinline__ u64 packdup(float v) {
    u64 r; asm("mov.b64 %0, {%1, %1};" : "=l"(r) : "f"(v));
    return r;
}
__device__ __forceinline__ void unpack2f(u64 p, float& lo, float& hi) {
    asm("mov.b64 {%0, %1}, %2;" : "=f"(lo), "=f"(hi) : "l"(p));
}

// ---------------- kernel: build half2 input planes ----------------
__global__ void build_in2_kernel(const float* __restrict__ x,
                                 const float* __restrict__ ms,
                                 const float* __restrict__ lpan,
                                 const float* __restrict__ pan,
                                 const float* __restrict__ s)
{
    int idx = blockIdx.x * 256 + threadIdx.x;
    if (idx >= Bc * NPLANES * HWp) return;
    int p  = idx % HWp;
    int t  = idx / HWp;
    int pl = t % NPLANES;
    int b  = t / NPLANES;
    float lo = 0.0f, hi = 0.0f;
    if (pl < 64) {
        lo = x[((size_t)b * CC + 2 * pl)     * HWp + p];
        hi = x[((size_t)b * CC + 2 * pl + 1) * HWp + p];
    } else {
        int g = (pl - 64) >> 3;
        int e = (pl - 64) & 7;
        float lp = lpan[b * HWp + p];
        if (g == 0) {
            if (e < 4) {
                float sv = s[b];
                lo = lp * (1.0f - sv) + ms[(b * 8 + 2 * e)     * HWp + p] * sv;
                hi = lp * (1.0f - sv) + ms[(b * 8 + 2 * e + 1) * HWp + p] * sv;
            }
        } else if (g == 1) {
            if (e == 0) lo = lp;
        } else if (g == 2) {
            if (e == 0)      { lo = lp; hi = pan[b * HWp + p]; }
            else if (e == 1) { lo = pan[b * HWp + p] - lp; }
        } else {
            if (e < 4) {
                lo = ms[(b * 8 + 2 * e)     * HWp + p];
                hi = ms[(b * 8 + 2 * e + 1) * HWp + p];
            }
        }
    }
    g_in2[idx] = packh2(lo, hi);
}

// ---------------- kernel: pack weights to half2 ----------------
__global__ void pack_w2_kernel(const float* __restrict__ q_w,
                               const float* __restrict__ k_pan_w,
                               const float* __restrict__ v_pan_w,
                               const float* __restrict__ kv_ms_w,
                               const float* __restrict__ proj_pan_w,
                               const float* __restrict__ proj_ms_w)
{
    const int TOT_C = 5 * 9 * 72 * 128;
    int idx = blockIdx.x * 256 + threadIdx.x;
    if (idx < TOT_C) {
        int cid  = idx / (9 * 72 * 128);
        int rem  = idx % (9 * 72 * 128);
        int tap  = rem / (72 * 128);
        int rem2 = rem % (72 * 128);
        int kp   = rem2 / 128;
        int oc   = rem2 % 128;
        const float* src; int cin;
        switch (cid) {
            case 0:  src = q_w;                      cin = 136; break;
            case 1:  src = k_pan_w;                  cin = 129; break;
            case 2:  src = v_pan_w;                  cin = 131; break;
            case 3:  src = kv_ms_w;                  cin = 136; break;
            default: src = kv_ms_w + 128 * 136 * 9;  cin = 136; break;
        }
        int k0 = 2 * kp, k1 = 2 * kp + 1;
        float lo = (k0 < cin) ? src[((size_t)oc * cin + k0) * 9 + tap] : 0.0f;
        float hi = (k1 < cin) ? src[((size_t)oc * cin + k1) * 9 + tap] : 0.0f;
        g_wt2[idx] = packh2(lo, hi);
    } else {
        int r = idx - TOT_C;
        if (r >= 2 * 64 * 128) return;
        int sd = r / (64 * 128);
        int kp = (r % (64 * 128)) / 128;
        int oc = r % 128;
        int n  = kp >> 3, dp = kp & 7;
        int k0 = n * 16 + dp, k1 = k0 + 8;     // (d, d+8) pair within head
        const float* src = sd ? proj_ms_w : proj_pan_w;
        g_wtp2[r] = packh2(src[oc * 128 + k0], src[oc * 128 + k1]);
    }
}

// ---------------- fp16 mma conv kernel (256 thr, M=64, 2 CTAs/SM) ----
struct MCfg {
    const unsigned* inp;     // half2 plane base
    long long inBStride;     // per-batch stride (half2 elements)
    int group;               // extras-plane group (conv9)
    const unsigned* wt;      // [TAPS][KPAIRS][128] half2
    const float* bias;
    float* out;              // TAPS==9: float2 pair-plane base; TAPS==1: planar fp32
    long long outBStride;    // TAPS==9: float2 units; TAPS==1: float units
    float scale;
};
struct MParams { MCfg c[5]; };

// block 256 thr = 8 warps (2M x 4N). M = 64 oc (grid.y = oc half),
// N = 256 px = 2 rows x 128 cols. grid: x = 64 row-pairs, y = 2, z = nconv*Bc
template<int TAPS, int HALO, int KPAIRS>
__global__ __launch_bounds__(256, 2)
void conv_mma_kernel(MParams P)
{
    constexpr int NCH     = KPAIRS / 8;
    constexpr int ROWS_ST = 2 + 2 * HALO;
    constexpr int COLS_ST = 128 + 8 * HALO;
    constexpr int PSTR    = ROWS_ST * COLS_ST + 8;
    constexpr int OCS     = 72;                       // smem oc stride (mod 32 == 8)
    constexpr int COFF    = 3 * HALO;
    constexpr int VIN     = COLS_ST / 4;
    constexpr int SIN_SZ  = 8 * PSTR;
    constexpr int SW_SZ   = TAPS * 8 * OCS;
    constexpr int NIT_IN  = 8 * ROWS_ST * VIN;
    constexpr int NIT_W   = TAPS * 8 * 16;            // 16 cp16 per k-row of 64 oc

    extern __shared__ unsigned smem[];
    unsigned* sIn = smem;
    unsigned* sW  = smem + 2 * SIN_SZ;

    const int tid  = threadIdx.x;
    const int lane = tid & 31;
    const int wid  = tid >> 5;            // 0..7
    const int wm   = wid & 1;             // M half within block (2 x 32 oc)
    const int wn   = wid >> 1;            // 0..3
    const int r    = wn >> 1;             // row of pair
    const int cbase = (wn & 1) * 64;      // col half

    const int z   = blockIdx.z;
    const int b   = z % Bc;
    const MCfg cfg = P.c[z / Bc];
    const int oc0 = blockIdx.y * 64;
    const int ty0 = blockIdx.x * 2;

    const unsigned sInAddr = smem_u32(sIn);
    const unsigned sWAddr  = smem_u32(sW);

    float acc[2][8][4];
#pragma unroll
    for (int ti = 0; ti < 2; ti++)
#pragma unroll
        for (int j = 0; j < 8; j++)
#pragma unroll
            for (int q = 0; q < 4; q++) acc[ti][j][q] = 0.0f;

    const unsigned* inB = cfg.inp + (long long)b * cfg.inBStride;

    auto stage = [&](int ch, int bufsel) {
        const int c0 = ch * 8;
        unsigned dIn = sInAddr + (unsigned)bufsel * SIN_SZ * 4;
        for (int i = tid; i < NIT_IN; i += 256) {
            int ci  = i / (ROWS_ST * VIN);
            int rem = i % (ROWS_ST * VIN);
            int row = rem / VIN;
            int v   = rem % VIN;
            int gy  = ty0 + row - HALO;
            int gx  = 4 * v - 4 * HALO;
            int cp  = c0 + ci;
            int pl  = (cp < 64) ? cp : (64 + cfg.group * 8 + (cp - 64));
            const unsigned* src = inB + (long long)pl * HWp + gy * WW + gx;
            bool ok = (gy >= 0) && (gy < HH) && (gx >= 0) && (gx < WW);
            cp16(dIn + (unsigned)(ci * PSTR + row * COLS_ST + 4 * v) * 4, src, ok);
        }
        unsigned dW = sWAddr + (unsigned)bufsel * SW_SZ * 4;
        for (int i = tid; i < NIT_W; i += 256) {
            int tap = i >> 7;             // / 128
            int rem = i & 127;
            int k   = rem >> 4;           // / 16
            int v   = rem & 15;
            const unsigned* src = cfg.wt + ((long long)tap * KPAIRS + (c0 + k)) * 128
                                + oc0 + 4 * v;
            cp16(dW + (unsigned)((tap * 8 + k) * OCS + 4 * v) * 4, src, true);
        }
    };

    stage(0, 0);
    cp_commit();

    const int kk   = lane & 3;
    const int mrow = lane >> 2;
    const int ocA0 = wm * 32 + mrow;
    const int ib0  = kk * PSTR + r * COLS_ST + cbase + COFF + mrow;

    for (int ch = 0; ch < NCH; ch++) {
        if (ch + 1 < NCH) { stage(ch + 1, (ch + 1) & 1); cp_commit(); cp_wait<1>(); }
        else              { cp_wait<0>(); }
        __syncthreads();

        const unsigned* bufIn = sIn + (ch & 1) * SIN_SZ;
        const unsigned* bufW  = sW  + (ch & 1) * SW_SZ;

#pragma unroll
        for (int tap = 0; tap < TAPS; tap++) {
            const int dy = (TAPS == 9) ? tap / 3 : 0;
            const int dx = (TAPS == 9) ? tap % 3 : 0;

            const unsigned* wb = bufW + (tap * 8 + kk) * OCS;
            unsigned a0 = wb[ocA0];
            unsigned a1 = wb[ocA0 + 8];
            unsigned a2 = wb[4 * OCS + ocA0];
            unsigned a3 = wb[4 * OCS + ocA0 + 8];
            unsigned c0_ = wb[ocA0 + 16];
            unsigned c1_ = wb[ocA0 + 24];
            unsigned c2_ = wb[4 * OCS + ocA0 + 16];
            unsigned c3_ = wb[4 * OCS + ocA0 + 24];

            const unsigned* ibp = bufIn + ib0 + dy * COLS_ST + dx;
            unsigned bf[8][2];
#pragma unroll
            for (int j = 0; j < 8; j++) {
                bf[j][0] = ibp[j * 8];
                bf[j][1] = ibp[4 * PSTR + j * 8];
            }
#pragma unroll
            for (int j = 0; j < 8; j++) {
                mma_f16(acc[0][j], a0, a1, a2, a3, bf[j][0], bf[j][1]);
                mma_f16(acc[1][j], c0_, c1_, c2_, c3_, bf[j][0], bf[j][1]);
            }
        }
        __syncthreads();
    }

    // ---- epilogue ----
    const int mr = lane >> 2;
    if (TAPS == 9) {
        // paired float2 pair-planes: plane = head*8 + mr, pair = (oc, oc+8)
#pragma unroll
        for (int ti = 0; ti < 2; ti++) {
            int head = (oc0 >> 4) + 2 * wm + ti;
            int oc   = head * 16 + mr;
            float b0 = cfg.bias[oc];
            float b1 = cfg.bias[oc + 8];
            float2* po = (float2*)cfg.out + (long long)b * cfg.outBStride
                       + (long long)(head * 8 + mr) * HWp + (ty0 + r) * WW;
#pragma unroll
            for (int j = 0; j < 8; j++) {
                int col = cbase + j * 8 + (lane & 3) * 2;
                float4 v = { (acc[ti][j][0] + b0) * cfg.scale,
                             (acc[ti][j][2] + b1) * cfg.scale,
                             (acc[ti][j][1] + b0) * cfg.scale,
                             (acc[ti][j][3] + b1) * cfg.scale };
                *(float4*)(po + col) = v;
            }
        }
    } else {
        float* outB = cfg.out + (long long)b * cfg.outBStride + (ty0 + r) * WW;
#pragma unroll
        for (int ti = 0; ti < 2; ti++) {
            int ocb = oc0 + wm * 32 + ti * 16 + mr;
            float b0 = cfg.bias[ocb];
            float b1 = cfg.bias[ocb + 8];
#pragma unroll
            for (int j = 0; j < 8; j++) {
                int col = cbase + j * 8 + (lane & 3) * 2;
                float* o0 = outB + (long long)ocb * HWp + col;
                float2 w0 = { (acc[ti][j][0] + b0) * cfg.scale,
                              (acc[ti][j][1] + b0) * cfg.scale };
                *(float2*)o0 = w0;
                float* o8 = o0 + 8 * HWp;
                float2 w1 = { (acc[ti][j][2] + b1) * cfg.scale,
                              (acc[ti][j][3] + b1) * cfg.scale };
                *(float2*)o8 = w1;
            }
        }
    }
}

// ---------------- kernel: fused depthwise + attention (pair-plane I/O) -----
#define TLW 34
#define TLH 18
__global__ __launch_bounds__(256)
void attn_kernel(const u64* __restrict__ q2,
                 const u64* __restrict__ KV2,
                 const float* __restrict__ dw,
                 const float* __restrict__ db,
                 unsigned* __restrict__ O2,
                 int sidx)
{
    __shared__ u64 sTile[8][TLH][TLW];
    __shared__ u64 sW2[8][9][9];
    __shared__ u64 sB2[8][9];

    const int tid = threadIdx.y * 32 + threadIdx.x;
    const int tx  = threadIdx.x;
    const int ty  = threadIdx.y;

    const int bn = blockIdx.x;
    const int b  = bn / NHh;
    const int n  = bn % NHh;
    const int s  = sidx;
    const int x0 = (blockIdx.y & 3) * 32;
    const int y0 = (blockIdx.y >> 2) * 16;

    // weights paired (d, d+8)
    for (int i = tid; i < 8 * 9 * 9; i += 256) {
        int dp = i / 81, a = (i / 9) % 9, t = i % 9;
        ((u64*)sW2)[i] = pack2f(dw[(dp * 9 + a) * 9 + t],
                                dw[((dp + 8) * 9 + a) * 9 + t]);
    }
    for (int i = tid; i < 72; i += 256) {
        int dp = i / 9, a = i % 9;
        ((u64*)sB2)[i] = pack2f(db[dp * 9 + a], db[(dp + 8) * 9 + a]);
    }

    const int py0 = y0 + 2 * ty;
    const int px  = x0 + tx;
    const int p0  = py0 * WW + px;
    const u64* qB = q2 + ((size_t)b * 64 + n * 8) * HWp;

    auto loadTile = [&](const u64* base) {
        for (int i = tid; i < 8 * TLH * TLW; i += 256) {
            int dp = i / (TLH * TLW);
            int rr = (i / TLW) % TLH;
            int cc = i % TLW;
            int gy = y0 + rr - 1, gx = x0 + cc - 1;
            u64 v = 0ull;
            if (gy >= 0 && gy < HH && gx >= 0 && gx < WW)
                v = base[(size_t)dp * HWp + gy * WW + gx];
            sTile[dp][rr][cc] = v;
        }
    };

    const u64* Kbase = KV2 + (((size_t)(2 * s)     * Bc + b) * 64 + n * 8) * HWp;
    const u64* Vbase = KV2 + (((size_t)(2 * s + 1) * Bc + b) * 64 + n * 8) * HWp;

    // ---- K phase ----
    loadTile(Kbase);
    __syncthreads();

    u64 logits2[2][9];
#pragma unroll
    for (int j = 0; j < 2; j++)
#pragma unroll
        for (int a = 0; a < 9; a++) logits2[j][a] = 0ull;

    for (int dp = 0; dp < 8; dp++) {
        const u64* qp = qB + (size_t)dp * HWp + p0;
        u64 q2_0 = qp[0];
        u64 q2_1 = qp[WW];
#pragma unroll
        for (int a = 0; a < 9; a++) {
            u64 b2 = sB2[dp][a];
            ffma2(logits2[0][a], q2_0, b2);
            ffma2(logits2[1][a], q2_1, b2);
        }
#pragma unroll
        for (int dx = 0; dx < 3; dx++) {
            u64 m0 = sTile[dp][2 * ty + 0][tx + dx];
            u64 m1 = sTile[dp][2 * ty + 1][tx + dx];
            u64 m2 = sTile[dp][2 * ty + 2][tx + dx];
            u64 m3 = sTile[dp][2 * ty + 3][tx + dx];
            u64 mq00 = mul2(q2_0, m0), mq01 = mul2(q2_0, m1), mq02 = mul2(q2_0, m2);
            u64 mq10 = mul2(q2_1, m1), mq11 = mul2(q2_1, m2), mq12 = mul2(q2_1, m3);
#pragma unroll
            for (int dy = 0; dy < 3; dy++) {
                int t = dy * 3 + dx;
                u64 a0 = (dy == 0) ? mq00 : (dy == 1) ? mq01 : mq02;
                u64 a1 = (dy == 0) ? mq10 : (dy == 1) ? mq11 : mq12;
#pragma unroll
                for (int a = 0; a < 9; a++) {
                    u64 w = sW2[dp][a][t];
                    ffma2(logits2[0][a], a0, w);
                    ffma2(logits2[1][a], a1, w);
                }
            }
        }
    }

    // ---- softmax ----
    u64 attn2[2][9];
#pragma unroll
    for (int j = 0; j < 2; j++) {
        float lg[9];
#pragma unroll
        for (int a = 0; a < 9; a++) {
            float lo, hi; unpack2f(logits2[j][a], lo, hi);
            lg[a] = lo + hi;
        }
        float m = lg[0];
#pragma unroll
        for (int a = 1; a < 9; a++) m = fmaxf(m, lg[a]);
        float sum = 0.0f;
#pragma unroll
        for (int a = 0; a < 9; a++) { lg[a] = __expf(lg[a] - m); sum += lg[a]; }
        float inv = 1.0f / sum;
#pragma unroll
        for (int a = 0; a < 9; a++) attn2[j][a] = packdup(lg[a] * inv);
    }

    // ---- V phase ----
    __syncthreads();
    loadTile(Vbase);
    __syncthreads();

    for (int dp = 0; dp < 8; dp++) {
        u64 m[4][3];
#pragma unroll
        for (int rr = 0; rr < 4; rr++)
#pragma unroll
            for (int cc = 0; cc < 3; cc++)
                m[rr][cc] = sTile[dp][2 * ty + rr][tx + cc];

        u64 out2_0 = 0ull, out2_1 = 0ull;
#pragma unroll
        for (int a = 0; a < 9; a++) {
            u64 b2 = sB2[dp][a];
            u64 v0 = b2, v1 = b2;
#pragma unroll
            for (int t = 0; t < 9; t++) {
                u64 w = sW2[dp][a][t];
                int dy = t / 3, dx = t % 3;
                ffma2(v0, m[dy][dx],     w);
                ffma2(v1, m[dy + 1][dx], w);
            }
            ffma2(out2_0, attn2[0][a], v0);
            ffma2(out2_1, attn2[1][a], v1);
        }

        float lo, hi;
        unsigned* oB = O2 + (((size_t)b * 2 + s) * 64 + n * 8 + dp) * HWp;
        unpack2f(out2_0, lo, hi);
        oB[p0] = packh2(lo, hi);
        unpack2f(out2_1, lo, hi);
        oB[p0 + WW] = packh2(lo, hi);
    }
}

// ---------------- launch ----------------
extern "C" void kernel_launch(void* const* d_in, const int* in_sizes, int n_in,
                              void* d_out, int out_size)
{
    const float* x        = (const float*)d_in[0];
    const float* ms       = (const float*)d_in[1];
    const float* lpan     = (const float*)d_in[2];
    const float* pan      = (const float*)d_in[3];
    const float* s        = (const float*)d_in[4];
    const float* q_w      = (const float*)d_in[5];
    const float* q_b      = (const float*)d_in[6];
    const float* k_pan_w  = (const float*)d_in[7];
    const float* k_pan_b  = (const float*)d_in[8];
    const float* v_pan_w  = (const float*)d_in[9];
    const float* v_pan_b  = (const float*)d_in[10];
    const float* kv_ms_w  = (const float*)d_in[11];
    const float* kv_ms_b  = (const float*)d_in[12];
    const float* dep_w    = (const float*)d_in[13];
    const float* dep_b    = (const float*)d_in[14];
    const float* proj_pan_w = (const float*)d_in[15];
    const float* proj_pan_b = (const float*)d_in[16];
    const float* proj_ms_w  = (const float*)d_in[17];
    const float* proj_ms_b  = (const float*)d_in[18];

    unsigned *gin2, *gwt2, *gwtp2, *o2;
    u64 *q2, *kv2;
    cudaGetSymbolAddress((void**)&gin2,  g_in2);
    cudaGetSymbolAddress((void**)&gwt2,  g_wt2);
    cudaGetSymbolAddress((void**)&gwtp2, g_wtp2);
    cudaGetSymbolAddress((void**)&q2,    g_q2);
    cudaGetSymbolAddress((void**)&kv2,   g_KV2);
    cudaGetSymbolAddress((void**)&o2,    g_O2);

    // smem: conv9: (2*8*552 + 2*9*8*72)*4 = 76800 B ; proj: (2*8*264 + 2*8*72)*4 = 21504 B
    const int SMEM9 = (2 * 8 * 552 + 2 * 9 * 8 * 72) * 4;
    const int SMEM1 = (2 * 8 * 264 + 2 * 1 * 8 * 72) * 4;
    cudaFuncSetAttribute(conv_mma_kernel<9, 1, 72>,
                         cudaFuncAttributeMaxDynamicSharedMemorySize, SMEM9);
    cudaFuncSetAttribute(conv_mma_kernel<1, 0, 64>,
                         cudaFuncAttributeMaxDynamicSharedMemorySize, SMEM1);

    const long long INBS  = (long long)NPLANES * HWp;   // conv input batch stride (half2)
    const long long PSTRM = 64LL * Bc * HWp;            // one KV stream-part (u64 planes)

    // stream-A convs: q, k_pan, v_pan (paired float2 outputs)
    MParams PA = {};
    PA.c[0] = { gin2, INBS, 0, gwt2 + 0LL * 9 * 72 * 128, q_b,
                (float*)q2,                 64LL * HWp, SCALEF };
    PA.c[1] = { gin2, INBS, 1, gwt2 + 1LL * 9 * 72 * 128, k_pan_b,
                (float*)(kv2 + 0LL * PSTRM), 64LL * HWp, 1.0f };
    PA.c[2] = { gin2, INBS, 2, gwt2 + 2LL * 9 * 72 * 128, v_pan_b,
                (float*)(kv2 + 1LL * PSTRM), 64LL * HWp, 1.0f };
    // stream-B convs: kv_ms halves
    MParams PB = {};
    PB.c[0] = { gin2, INBS, 3, gwt2 + 3LL * 9 * 72 * 128, kv_ms_b,
                (float*)(kv2 + 2LL * PSTRM), 64LL * HWp, 1.0f };
    PB.c[1] = { gin2, INBS, 3, gwt2 + 4LL * 9 * 72 * 128, kv_ms_b + 128,
                (float*)(kv2 + 3LL * PSTRM), 64LL * HWp, 1.0f };

    // projection (planar fp32 output to d_out)
    float* dout = (float*)d_out;
    MParams PP = {};
    PP.c[0] = { o2,            2LL * 64 * HWp, 0, gwtp2,            proj_pan_b,
                dout,                            (long long)CC * HWp, 1.0f };
    PP.c[1] = { o2 + 64 * HWp, 2LL * 64 * HWp, 0, gwtp2 + 64 * 128, proj_ms_b,
                dout + (long long)Bc * CC * HWp, (long long)CC * HWp, 1.0f };

    const int nIn = Bc * NPLANES * HWp;
    const int nW  = 5 * 9 * 72 * 128 + 2 * 64 * 128;

    cudaStream_t sB = 0;
    cudaEvent_t evRoot = 0, evB = 0, evP = 0, evQ = 0, evM = 0;
    bool par = true;
    par = par && (cudaStreamCreateWithFlags(&sB, cudaStreamNonBlocking) == cudaSuccess);
    par = par && (cudaEventCreateWithFlags(&evRoot, cudaEventDisableTiming) == cudaSuccess);
    par = par && (cudaEventCreateWithFlags(&evB,    cudaEventDisableTiming) == cudaSuccess);
    par = par && (cudaEventCreateWithFlags(&evP,    cudaEventDisableTiming) == cudaSuccess);
    par = par && (cudaEventCreateWithFlags(&evQ,    cudaEventDisableTiming) == cudaSuccess);
    par = par && (cudaEventCreateWithFlags(&evM,    cudaEventDisableTiming) == cudaSuccess);

    if (par) {
        cudaEventRecord(evRoot, 0);
        cudaStreamWaitEvent(sB, evRoot, 0);

        build_in2_kernel<<<(nIn + 255) / 256, 256, 0, 0>>>(x, ms, lpan, pan, s);
        cudaEventRecord(evB, 0);
        pack_w2_kernel<<<(nW + 255) / 256, 256, 0, sB>>>(q_w, k_pan_w, v_pan_w, kv_ms_w,
                                                         proj_pan_w, proj_ms_w);
        cudaEventRecord(evP, sB);

        cudaStreamWaitEvent(0, evP, 0);
        conv_mma_kernel<9, 1, 72><<<dim3(64, 2, 3 * Bc), 256, SMEM9, 0>>>(PA);
        cudaEventRecord(evQ, 0);
        cudaStreamWaitEvent(sB, evB, 0);
        conv_mma_kernel<9, 1, 72><<<dim3(64, 2, 2 * Bc), 256, SMEM9, sB>>>(PB);

        attn_kernel<<<dim3(Bc * NHh, 32), dim3(32, 8), 0, 0>>>(q2, kv2, dep_w, dep_b, o2, 0);
        cudaStreamWaitEvent(sB, evQ, 0);
        attn_kernel<<<dim3(Bc * NHh, 32), dim3(32, 8), 0, sB>>>(q2, kv2, dep_w, dep_b, o2, 1);
        cudaEventRecord(evM, sB);

        cudaStreamWaitEvent(0, evM, 0);
        conv_mma_kernel<1, 0, 64><<<dim3(64, 2, 2 * Bc), 256, SMEM1, 0>>>(PP);
    } else {
        build_in2_kernel<<<(nIn + 255) / 256, 256>>>(x, ms, lpan, pan, s);
        pack_w2_kernel<<<(nW + 255) / 256, 256>>>(q_w, k_pan_w, v_pan_w, kv_ms_w,
                                                  proj_pan_w, proj_ms_w);
        conv_mma_kernel<9, 1, 72><<<dim3(64, 2, 3 * Bc), 256, SMEM9>>>(PA);
        conv_mma_kernel<9, 1, 72><<<dim3(64, 2, 2 * Bc), 256, SMEM9>>>(PB);
        attn_kernel<<<dim3(Bc * NHh, 32), dim3(32, 8)>>>(q2, kv2, dep_w, dep_b, o2, 0);
        attn_kernel<<<dim3(Bc * NHh, 32), dim3(32, 8)>>>(q2, kv2, dep_w, dep_b, o2, 1);
        conv_mma_kernel<1, 0, 64><<<dim3(64, 2, 2 * Bc), 256, SMEM1>>>(PP);
    }
}